// round 5
// baseline (speedup 1.0000x reference)
#include <cuda_runtime.h>
#include <cuda_bf16.h>
#include <math.h>

// Problem constants
#define TSEQ 512
#define BATCH 128
#define DIMD 256
#define HID 128
#define G4 512      // 4*H
#define LBL 4

// ---------------- scratch (device globals; no allocation allowed) ----------------
__device__ float d_Xg[(size_t)2 * TSEQ * BATCH * G4];      // 268 MB: input gates + biases, [dir][t][b][512]
__device__ float d_hbuf[(size_t)TSEQ * BATCH * 2 * HID];   // 67 MB: [t][b][256] = concat(hf, hb)
__device__ float d_scores[(size_t)TSEQ * BATCH * LBL];     // 1 MB:  [t][b][4]
__device__ unsigned d_btbuf[(size_t)TSEQ * BATCH];         // 256 KB: packed backtrace (2 bits/label)

__device__ __forceinline__ float sigm(float x) { return 1.f / (1.f + expf(-x)); }

// ============================================================================
// Kernel 1: embedding gather + Xg = x @ W_ih^T + (b_ih + b_hh), both directions
// Grid (512 m-tiles = timesteps, 8 n-tiles: 4 fwd + 4 bwd), 256 threads.
// Tile 128x128, K=256, plain fp32 FFMA.
// ============================================================================
__global__ void __launch_bounds__(256) k_gemm(
    const int* __restrict__ pad_seq, const float* __restrict__ emb,
    const float* __restrict__ Wihf, const float* __restrict__ Wihb,
    const float* __restrict__ bihf, const float* __restrict__ bhhf,
    const float* __restrict__ bihb, const float* __restrict__ bhhb)
{
    __shared__ float As[16][128];   // [k][m]  m = batch row
    __shared__ float Bs[16][128];   // [k][n]  n = gate row
    __shared__ int   tok[128];

    const int tid = threadIdx.x;
    const int mt  = blockIdx.x;          // timestep t
    const int nt  = blockIdx.y;          // 0..7
    const int dir = nt >> 2;
    const int gbase = (nt & 3) * 128;    // gate column base within direction
    const float* __restrict__ W = dir ? Wihb : Wihf;

    if (tid < 128) tok[tid] = pad_seq[tid * TSEQ + mt];   // pad_seq[b][t]

    const int tx = tid & 15, ty = tid >> 4;
    float acc[8][8];
#pragma unroll
    for (int i = 0; i < 8; ++i)
#pragma unroll
        for (int jj = 0; jj < 8; ++jj) acc[i][jj] = 0.f;

    __syncthreads();

    for (int kt = 0; kt < 16; ++kt) {
        const int k0 = kt * 16;
        for (int e = tid; e < 512; e += 256) {
            const int row = e >> 2;            // 0..127
            const int kq  = (e & 3) * 4;       // 0,4,8,12
            const float4 av = *reinterpret_cast<const float4*>(
                &emb[(size_t)tok[row] * DIMD + k0 + kq]);
            As[kq + 0][row] = av.x; As[kq + 1][row] = av.y;
            As[kq + 2][row] = av.z; As[kq + 3][row] = av.w;
            const float4 bv = *reinterpret_cast<const float4*>(
                &W[(size_t)(gbase + row) * DIMD + k0 + kq]);
            Bs[kq + 0][row] = bv.x; Bs[kq + 1][row] = bv.y;
            Bs[kq + 2][row] = bv.z; Bs[kq + 3][row] = bv.w;
        }
        __syncthreads();
#pragma unroll
        for (int kk = 0; kk < 16; ++kk) {
            const float4 a0 = *reinterpret_cast<const float4*>(&As[kk][ty * 8]);
            const float4 a1 = *reinterpret_cast<const float4*>(&As[kk][ty * 8 + 4]);
            const float4 w0 = *reinterpret_cast<const float4*>(&Bs[kk][tx * 8]);
            const float4 w1 = *reinterpret_cast<const float4*>(&Bs[kk][tx * 8 + 4]);
            const float ar[8] = {a0.x, a0.y, a0.z, a0.w, a1.x, a1.y, a1.z, a1.w};
            const float br[8] = {w0.x, w0.y, w0.z, w0.w, w1.x, w1.y, w1.z, w1.w};
#pragma unroll
            for (int i = 0; i < 8; ++i)
#pragma unroll
                for (int jj = 0; jj < 8; ++jj)
                    acc[i][jj] = fmaf(ar[i], br[jj], acc[i][jj]);
        }
        __syncthreads();
    }

    // epilogue: add (b_ih + b_hh)
    const float* bi = dir ? bihb : bihf;
    const float* bh = dir ? bhhb : bhhf;
    float bias[8];
#pragma unroll
    for (int jj = 0; jj < 8; ++jj) {
        const int g = gbase + tx * 8 + jj;
        bias[jj] = bi[g] + bh[g];
    }
#pragma unroll
    for (int i = 0; i < 8; ++i) {
        const int brow = ty * 8 + i;   // batch index
        float* o = d_Xg + (size_t)dir * ((size_t)TSEQ * BATCH * G4)
                 + (size_t)mt * (BATCH * G4) + (size_t)brow * G4 + gbase + tx * 8;
        float4 o0 = {acc[i][0] + bias[0], acc[i][1] + bias[1],
                     acc[i][2] + bias[2], acc[i][3] + bias[3]};
        float4 o1 = {acc[i][4] + bias[4], acc[i][5] + bias[5],
                     acc[i][6] + bias[6], acc[i][7] + bias[7]};
        *reinterpret_cast<float4*>(o)     = o0;
        *reinterpret_cast<float4*>(o + 4) = o1;
    }
}

// ============================================================================
// Kernel 2: bidirectional LSTM recurrence. One block per batch element.
// 512 threads: thread j owns gate row j of W_hh [512,128].
// Weight split: cols 0..95 in registers (96 floats), cols 96..127 in shared
// (32 cols x 512 threads as plain floats, 64 KB). h read from shared float4.
// Per step: g_j = Xg_j + sum_k Whh[j][k]*h[k]; threads <128 run activations.
// Forward pass then backward pass in the same block.
// ============================================================================
__global__ void __launch_bounds__(512, 1) k_lstm(
    const int* __restrict__ lens,
    const float* __restrict__ Whhf, const float* __restrict__ Whhb)
{
    extern __shared__ char smp[];
    float* ws  = reinterpret_cast<float*>(smp);               // 32*512 floats = 65536 B
    float* h_s = reinterpret_cast<float*>(smp + 65536);       // 128 floats
    float* g_s = reinterpret_cast<float*>(smp + 65536 + 512); // 512 floats

    const int j = threadIdx.x;
    const int b = blockIdx.x;
    const int len = lens[b];

    for (int dir = 0; dir < 2; ++dir) {
        const float* __restrict__ wrow = (dir ? Whhb : Whhf) + (size_t)j * HID;
        float wr[96];
#pragma unroll
        for (int p = 0; p < 96; ++p) wr[p] = wrow[p];          // cols 0..95
#pragma unroll
        for (int c4 = 0; c4 < 32; ++c4) ws[c4 * 512 + j] = wrow[96 + c4]; // cols 96..127
        if (j < HID) h_s[j] = 0.f;
        float c = 0.f;
        __syncthreads();

        const float* xgb = d_Xg + (size_t)dir * ((size_t)TSEQ * BATCH * G4)
                         + (size_t)b * G4 + j;
        int t = dir ? (TSEQ - 1) : 0;
        const int stp = dir ? -1 : 1;
        float xg = xgb[(size_t)t * (BATCH * G4)];

        for (int it = 0; it < TSEQ; ++it) {
            const int tn = t + stp;
            float xgn = 0.f;
            if (it < TSEQ - 1) xgn = xgb[(size_t)tn * (BATCH * G4)];   // prefetch next step

            float acc = xg;
            const float4* h4 = reinterpret_cast<const float4*>(h_s);
#pragma unroll
            for (int q = 0; q < 24; ++q) {          // cols 0..95 from registers
                const float4 hv = h4[q];
                acc = fmaf(wr[4 * q + 0], hv.x, acc);
                acc = fmaf(wr[4 * q + 1], hv.y, acc);
                acc = fmaf(wr[4 * q + 2], hv.z, acc);
                acc = fmaf(wr[4 * q + 3], hv.w, acc);
            }
#pragma unroll
            for (int q = 0; q < 8; ++q) {           // cols 96..127 from shared
                const float4 hv = h4[24 + q];
                acc = fmaf(ws[(4 * q + 0) * 512 + j], hv.x, acc);
                acc = fmaf(ws[(4 * q + 1) * 512 + j], hv.y, acc);
                acc = fmaf(ws[(4 * q + 2) * 512 + j], hv.z, acc);
                acc = fmaf(ws[(4 * q + 3) * 512 + j], hv.w, acc);
            }
            g_s[j] = acc;
            __syncthreads();

            if (j < HID) {
                const float gi = g_s[j];
                const float gf = g_s[j + 128];
                const float gc = g_s[j + 256];
                const float go = g_s[j + 384];
                const float i_ = sigm(gi);
                const float f_ = sigm(gf);
                const float o_ = sigm(go);
                const float c2 = f_ * c + i_ * tanhf(gc);
                const float h2 = o_ * tanhf(c2);
                const bool m = (t < len);
                d_hbuf[((size_t)t * BATCH + b) * (2 * HID) + dir * HID + j] = m ? h2 : 0.f;
                if (m) { c = c2; h_s[j] = h2; }
            }
            __syncthreads();
            xg = xgn;
            t = tn;
        }
        __syncthreads();   // protect ws/h_s reinit for next direction
    }
}

// ============================================================================
// Kernel 3: emissions  scores[t][b][l] = h[t][b][:] @ W_lab[l][:] + b_lab[l]
// One warp per (t,b) row. Grid 8192 blocks x 256 threads.
// ============================================================================
__global__ void __launch_bounds__(256) k_emis(
    const float* __restrict__ Wlab, const float* __restrict__ blab)
{
    __shared__ float wl[LBL * DIMD];
    const int tid = threadIdx.x;
    for (int e = tid; e < LBL * DIMD; e += 256) wl[e] = Wlab[e];
    __syncthreads();

    const int wid = tid >> 5, lane = tid & 31;
    const int m = blockIdx.x * 8 + wid;        // m = t*128 + b
    const float* h = d_hbuf + (size_t)m * (2 * HID);

    float a0 = 0.f, a1 = 0.f, a2 = 0.f, a3 = 0.f;
#pragma unroll
    for (int cch = 0; cch < 2; ++cch) {
        const int k = cch * 128 + lane * 4;
        const float4 hv = *reinterpret_cast<const float4*>(h + k);
        a0 += hv.x * wl[k]       + hv.y * wl[k + 1]       + hv.z * wl[k + 2]       + hv.w * wl[k + 3];
        a1 += hv.x * wl[256 + k] + hv.y * wl[256 + k + 1] + hv.z * wl[256 + k + 2] + hv.w * wl[256 + k + 3];
        a2 += hv.x * wl[512 + k] + hv.y * wl[512 + k + 1] + hv.z * wl[512 + k + 2] + hv.w * wl[512 + k + 3];
        a3 += hv.x * wl[768 + k] + hv.y * wl[768 + k + 1] + hv.z * wl[768 + k + 2] + hv.w * wl[768 + k + 3];
    }
#pragma unroll
    for (int off = 16; off; off >>= 1) {
        a0 += __shfl_down_sync(0xffffffffu, a0, off);
        a1 += __shfl_down_sync(0xffffffffu, a1, off);
        a2 += __shfl_down_sync(0xffffffffu, a2, off);
        a3 += __shfl_down_sync(0xffffffffu, a3, off);
    }
    if (lane == 0) {
        float4 o = {a0 + blab[0], a1 + blab[1], a2 + blab[2], a3 + blab[3]};
        *reinterpret_cast<float4*>(d_scores + (size_t)m * 4) = o;
    }
}

// ============================================================================
// Kernel 4: Viterbi forward + backtrace. 1 block, thread b = batch element.
// OUTPUT IS WRITTEN AS float32 (labels cast to float) — the comparison is a
// float relative-error, so the output buffer dtype is float32.
// ============================================================================
__global__ void __launch_bounds__(128) k_vit(
    const int* __restrict__ lens, const float* __restrict__ trans,
    const float* __restrict__ fromB, const float* __restrict__ toE,
    float* __restrict__ out)
{
    __shared__ float tr[16], fb[4], te[4];
    const int b = threadIdx.x;
    if (b < 16) tr[b] = trans[b];
    if (b < 4) { fb[b] = fromB[b]; te[b] = toE[b]; }
    __syncthreads();

    const int len = lens[b];
    const float4* sc = reinterpret_cast<const float4*>(d_scores);  // sc[t*128+b]

    const float4 e0 = sc[b];
    float best[4] = {fb[0] + e0.x, fb[1] + e0.y, fb[2] + e0.z, fb[3] + e0.w};

    // ---- forward ----
    for (int tc = 1; tc < TSEQ; tc += 8) {
        float4 eb[8];
#pragma unroll
        for (int u = 0; u < 8; ++u) {
            const int t = tc + u;
            if (t < TSEQ) eb[u] = sc[t * BATCH + b];
        }
#pragma unroll
        for (int u = 0; u < 8; ++u) {
            const int t = tc + u;
            if (t < TSEQ) {
                const float e[4] = {eb[u].x, eb[u].y, eb[u].z, eb[u].w};
                unsigned w = 0;
                float nb[4];
#pragma unroll
                for (int l = 0; l < 4; ++l) {
                    float mx = best[0] + tr[l];
                    int ar = 0;
#pragma unroll
                    for (int p = 1; p < 4; ++p) {
                        const float v = best[p] + tr[p * 4 + l];
                        if (v > mx) { mx = v; ar = p; }
                    }
                    nb[l] = mx + e[l];
                    w |= (unsigned)ar << (2 * l);
                }
                d_btbuf[t * BATCH + b] = w;
                if (t < len) { best[0] = nb[0]; best[1] = nb[1]; best[2] = nb[2]; best[3] = nb[3]; }
            }
        }
    }

    // ---- terminal ----
    const float fv[4] = {best[0] + te[0], best[1] + te[1], best[2] + te[2], best[3] + te[3]};
    int last = 0; float bm = fv[0];
#pragma unroll
    for (int l = 1; l < 4; ++l) if (fv[l] > bm) { bm = fv[l]; last = l; }

    // ---- backtrace (descending, prefetched) ----
    int lab = last;
    float* ob = out + (size_t)b * TSEQ;
    for (int tc = TSEQ - 1; tc >= 0; tc -= 8) {
        unsigned wbuf[8];
#pragma unroll
        for (int u = 0; u < 8; ++u) {
            const int t = tc - u;
            wbuf[u] = (t >= 0 && t < TSEQ - 1) ? d_btbuf[(t + 1) * BATCH + b] : 0u;
        }
#pragma unroll
        for (int u = 0; u < 8; ++u) {
            const int t = tc - u;
            if (t >= 0) {
                int v;
                if (t >= len) v = 0;
                else if (t == len - 1) { lab = last; v = lab; }
                else { lab = (int)((wbuf[u] >> (2 * lab)) & 3u); v = lab; }
                ob[t] = (float)v;   // float32 output
            }
        }
    }
}

// ============================================================================
extern "C" void kernel_launch(void* const* d_in, const int* in_sizes, int n_in,
                              void* d_out, int out_size)
{
    const int*   pad_seq = (const int*)  d_in[0];
    const int*   lens    = (const int*)  d_in[1];
    const float* emb     = (const float*)d_in[2];
    const float* Wihf    = (const float*)d_in[3];
    const float* Whhf    = (const float*)d_in[4];
    const float* bihf    = (const float*)d_in[5];
    const float* bhhf    = (const float*)d_in[6];
    const float* Wihb    = (const float*)d_in[7];
    const float* Whhb    = (const float*)d_in[8];
    const float* bihb    = (const float*)d_in[9];
    const float* bhhb    = (const float*)d_in[10];
    const float* Wlab    = (const float*)d_in[11];
    const float* blab    = (const float*)d_in[12];
    const float* trans   = (const float*)d_in[13];
    const float* fromB   = (const float*)d_in[14];
    const float* toE     = (const float*)d_in[15];
    float* out = (float*)d_out;

    const int lstm_smem = 65536 + 512 + 2048;   // ws + h_s + g_s = 68096 B
    cudaFuncSetAttribute(k_lstm, cudaFuncAttributeMaxDynamicSharedMemorySize, lstm_smem);

    k_gemm<<<dim3(TSEQ, 8), 256>>>(pad_seq, emb, Wihf, Wihb, bihf, bhhf, bihb, bhhb);
    k_lstm<<<BATCH, 512, lstm_smem>>>(lens, Whhf, Whhb);
    k_emis<<<(TSEQ * BATCH) / 8, 256>>>(Wlab, blab);
    k_vit<<<1, BATCH>>>(lens, trans, fromB, toE, out);
}